// round 14
// baseline (speedup 1.0000x reference)
#include <cuda_runtime.h>
#include <cuda_fp16.h>
#include <mma.h>
#include <math.h>
using namespace nvcuda;

#define EMB   1024
#define HID   2048
#define VOCAB 50257
#define T     256
#define ROWS_PER_BLK 8
#define NBLK1 ((VOCAB + ROWS_PER_BLK - 1) / ROWS_PER_BLK)   // 6283
#define NHHB  (4 * HID / ROWS_PER_BLK)                      // 1024
#define MAXCAND 512
#define NVB   ((VOCAB + 31) / 32)                           // 1571 final-pass col blocks

// Persistent device state (allocation-free scratch).
__device__ float g_h[2][HID];
__device__ __half g_h_half[HID];
__device__ float g_c[HID];
__device__ float g_hh[4 * HID];
__device__ __half g_H[(size_t)T * HID];              // all h's for the final GEMM
__device__ unsigned long long g_amax[T];             // EXACT packed argmax
__device__ unsigned long long g_amax2[T];            // max LOWER-bound key
__device__ unsigned long long g_blockbest[NBLK1];    // per-block max UPPER-bound key
__device__ float g_approx[VOCAB];                    // per-step upper bounds u(r)
__device__ float g_drow[VOCAB];                      // exact fp8 row error norms
__device__ float g_hnorm2[T];
__device__ unsigned g_wmax2;
__device__ int g_swap;                               // fp8 pair-order probe
__device__ unsigned char g_Wout_f8[(size_t)(VOCAB + 31) * HID];
__device__ __half g_Wout_h[(size_t)(VOCAB + 31) * HID];

__device__ __forceinline__ unsigned long long pack_key(float v, int row) {
    unsigned ub = __float_as_uint(v);
    ub = (ub & 0x80000000u) ? ~ub : (ub | 0x80000000u);
    return ((unsigned long long)ub << 32) |
           (unsigned long long)(0xFFFFFFFFu - (unsigned)row);
}
__device__ __forceinline__ float unpack_val(unsigned long long key) {
    unsigned t = (unsigned)(key >> 32);
    unsigned orig = (t & 0x80000000u) ? (t ^ 0x80000000u) : ~t;
    return __uint_as_float(orig);
}
__device__ __forceinline__ void ffma2(unsigned long long& acc,
                                      unsigned long long a, unsigned long long b) {
    asm("fma.rn.f32x2 %0, %1, %2, %3;" : "=l"(acc) : "l"(a), "l"(b), "l"(acc));
}
__device__ __forceinline__ float f32x2_sum(unsigned long long v) {
    float2 f = *reinterpret_cast<float2*>(&v);
    return f.x + f.y;
}
union f4u { float4 f; unsigned long long u[2]; };

__device__ __forceinline__ unsigned short f2_to_fp8x2(float hi, float lo) {
    unsigned short r;
    asm("cvt.rn.satfinite.e4m3x2.f32 %0, %1, %2;" : "=h"(r) : "f"(hi), "f"(lo));
    return r;
}
__device__ __forceinline__ __half2 fp8x2_to_h2(unsigned short v) {
    unsigned r;
    asm("cvt.rn.f16x2.e4m3x2 %0, %1;" : "=r"(r) : "h"(v));
    return *reinterpret_cast<__half2*>(&r);
}
// decode pair -> (even, odd) floats honoring probe order
__device__ __forceinline__ float2 dec_pair(unsigned short v, int sw) {
    __half2 d = fp8x2_to_h2(v);
    float lo = __low2float(d), hi = __high2float(d);
    return sw ? make_float2(hi, lo) : make_float2(lo, hi);
}

__global__ void init_kernel() {
    int i = blockIdx.x * blockDim.x + threadIdx.x;   // grid covers 8192
    if (i < HID) {
        g_h[0][i] = 0.0f; g_h[1][i] = 0.0f;
        g_h_half[i] = __float2half(0.0f);
        g_c[i] = 0.0f;
    }
    if (i < 4 * HID) g_hh[i] = 0.0f;
    if (i < T) { g_amax[i] = 0ULL; g_amax2[i] = 0ULL; g_hnorm2[i] = 0.0f; }
    if (i == 0) {
        g_wmax2 = 0u;
        __half2 dec = fp8x2_to_h2(f2_to_fp8x2(2.0f, 1.0f));  // intent: lo=1
        g_swap = (__low2float(dec) == 1.0f) ? 0 : 1;
    }
}

// ---------------------------------------------------------------------------
// Convert W_out -> fp16 + fp8(x64); per-row EXACT error norm drow; max ||w||^2.
// ---------------------------------------------------------------------------
__global__ void __launch_bounds__(256) convert_wout(const float* __restrict__ W) {
    __shared__ float swsum[8], swerr[8];
    const int sw = g_swap;
    float maxn = 0.0f;

    for (int r = blockIdx.x; r < VOCAB; r += gridDim.x) {
        const float4* __restrict__ src = (const float4*)(W + (size_t)r * HID);
        __half2* __restrict__ dsth = (__half2*)(g_Wout_h + (size_t)r * HID);
        unsigned* __restrict__ dst8 = (unsigned*)(g_Wout_f8 + (size_t)r * HID);
        float ss = 0.0f, dd = 0.0f;
        for (int i = threadIdx.x; i < HID / 4; i += 256) {
            float4 v = src[i];
            dsth[2 * i]     = __floats2half2_rn(v.x, v.y);
            dsth[2 * i + 1] = __floats2half2_rn(v.z, v.w);
            unsigned short u0 = f2_to_fp8x2(v.y * 64.0f, v.x * 64.0f);
            unsigned short u1 = f2_to_fp8x2(v.w * 64.0f, v.z * 64.0f);
            dst8[i] = (unsigned)u0 | ((unsigned)u1 << 16);
            float2 p0 = dec_pair(u0, sw), p1 = dec_pair(u1, sw);
            float e0 = v.x - p0.x * 0.015625f, e1 = v.y - p0.y * 0.015625f;
            float e2 = v.z - p1.x * 0.015625f, e3 = v.w - p1.y * 0.015625f;
            dd += e0 * e0 + e1 * e1 + e2 * e2 + e3 * e3;
            ss += v.x * v.x + v.y * v.y + v.z * v.z + v.w * v.w;
        }
        #pragma unroll
        for (int off = 16; off; off >>= 1) {
            ss += __shfl_down_sync(0xFFFFFFFFu, ss, off);
            dd += __shfl_down_sync(0xFFFFFFFFu, dd, off);
        }
        if ((threadIdx.x & 31) == 0) { swsum[threadIdx.x >> 5] = ss; swerr[threadIdx.x >> 5] = dd; }
        __syncthreads();
        if (threadIdx.x == 0) {
            float ts = 0.0f, td = 0.0f;
            #pragma unroll
            for (int i = 0; i < 8; i++) { ts += swsum[i]; td += swerr[i]; }
            if (ts > maxn) maxn = ts;
            g_drow[r] = sqrtf(td);
        }
        __syncthreads();
    }
    if (threadIdx.x == 0)
        atomicMax(&g_wmax2, __float_as_uint(maxn));
}

// ---------------------------------------------------------------------------
// step_rest: gates = W_ih @ x + g_hh + biases -> LSTM cell -> h(t).
// ---------------------------------------------------------------------------
__global__ void __launch_bounds__(256) step_rest_kernel(
    const float* __restrict__ emb, const float* __restrict__ W_ih,
    const float* __restrict__ b_ih, const float* __restrict__ b_hh, int step)
{
    __shared__ float sx[EMB];
    __shared__ float sg[2][4];

    int tok = 0;
    if (step > 0)
        tok = (int)(0xFFFFFFFFu - (unsigned)(g_amax[step - 1] & 0xFFFFFFFFull));

    float* __restrict__ hnext = g_h[(step + 1) & 1];
    const float* __restrict__ xrow = emb + (size_t)tok * EMB;
    for (int i = threadIdx.x; i < EMB; i += 256) sx[i] = xrow[i];
    __syncthreads();

    const int wid = threadIdx.x >> 5, lane = threadIdx.x & 31;
    const int jl = wid >> 2, gate = wid & 3;
    const int j = blockIdx.x * 2 + jl;
    const int row = gate * HID + j;

    unsigned long long accA = 0ULL, accB = 0ULL, accC = 0ULL, accD = 0ULL;
    const float4* __restrict__ w1 = (const float4*)(W_ih + (size_t)row * EMB);
    const float4* __restrict__ s4x = (const float4*)sx;
    #pragma unroll
    for (int k = 0; k < EMB / 256; k++) {
        f4u wa, wb, va, vb;
        wa.f = __ldcs(&w1[lane + 64 * k]);
        wb.f = __ldcs(&w1[lane + 32 + 64 * k]);
        va.f = s4x[lane + 64 * k];
        vb.f = s4x[lane + 32 + 64 * k];
        ffma2(accA, wa.u[0], va.u[0]);
        ffma2(accB, wa.u[1], va.u[1]);
        ffma2(accC, wb.u[0], vb.u[0]);
        ffma2(accD, wb.u[1], vb.u[1]);
    }
    float a = (f32x2_sum(accA) + f32x2_sum(accB)) + (f32x2_sum(accC) + f32x2_sum(accD));
    #pragma unroll
    for (int off = 16; off; off >>= 1)
        a += __shfl_down_sync(0xFFFFFFFFu, a, off);

    if (lane == 0) sg[jl][gate] = a + g_hh[row];
    __syncthreads();

    if (threadIdx.x < 2) {
        const int jj = blockIdx.x * 2 + threadIdx.x;
        float ipre = sg[threadIdx.x][0] + b_ih[jj]           + b_hh[jj];
        float fpre = sg[threadIdx.x][1] + b_ih[HID + jj]     + b_hh[HID + jj];
        float gpre = sg[threadIdx.x][2] + b_ih[2 * HID + jj] + b_hh[2 * HID + jj];
        float opre = sg[threadIdx.x][3] + b_ih[3 * HID + jj] + b_hh[3 * HID + jj];
        float ig = 1.0f / (1.0f + expf(-ipre));
        float fg = 1.0f / (1.0f + expf(-fpre));
        float gg = tanhf(gpre);
        float og = 1.0f / (1.0f + expf(-opre));
        float c = fg * g_c[jj] + ig * gg;
        float h = og * tanhf(c);
        g_c[jj] = c;
        hnext[jj] = h;
        __half hh16 = __float2half(h);
        g_h_half[jj] = hh16;
        g_H[(size_t)step * HID + jj] = hh16;
        atomicAdd(&g_hnorm2[step], h * h);
    }
}

// ---------------------------------------------------------------------------
// Fused: blocks [0,NBLK1) fp8 approx logits with PROVABLE per-row interval
// [mid-E, mid+E]; blocks [NBLK1,..) compute g_hh = W_hh @ h(t) in fp32.
// ---------------------------------------------------------------------------
__global__ void __launch_bounds__(256) fused_kernel(
    const float* __restrict__ W_hh, const float* __restrict__ b_out, int step)
{
    __shared__ float sbuf[HID];                      // 8KB
    __shared__ unsigned long long skeyU[ROWS_PER_BLK], skeyL[ROWS_PER_BLK];

    const int wid = threadIdx.x >> 5, lane = threadIdx.x & 31;

    if (blockIdx.x < NBLK1) {
        // -------- fp8 logits role --------
        __half2* sh2 = (__half2*)sbuf;
        const int sw = g_swap;
        const __half2* hg2 = (const __half2*)g_h_half;
        for (int i = threadIdx.x; i < HID / 2; i += 256) {
            __half2 v = hg2[i];
            sh2[i] = sw ? __lowhigh2highlow(v) : v;
        }
        __syncthreads();

        const int row = blockIdx.x * ROWS_PER_BLK + wid;
        unsigned long long keyU = 0ULL, keyL = 0ULL;
        if (row < VOCAB) {
            const uint4* __restrict__ wp = (const uint4*)(g_Wout_f8 + (size_t)row * HID);
            float a0 = 0.f, a1 = 0.f;
            #pragma unroll
            for (int it = 0; it < 2; it++) {
                uint4 wA = __ldcs(&wp[lane + 64 * it]);
                uint4 wB = __ldcs(&wp[lane + 32 + 64 * it]);
                const __half2* hA = sh2 + (lane + 64 * it) * 8;
                const __half2* hB = sh2 + (lane + 32 + 64 * it) * 8;
                __half2 c0 = __float2half2_rn(0.f), c1 = c0, c2 = c0, c3 = c0;
                c0 = __hfma2(fp8x2_to_h2((unsigned short)wA.x),         hA[0], c0);
                c1 = __hfma2(fp8x2_to_h2((unsigned short)(wA.x >> 16)), hA[1], c1);
                c2 = __hfma2(fp8x2_to_h2((unsigned short)wA.y),         hA[2], c2);
                c3 = __hfma2(fp8x2_to_h2((unsigned short)(wA.y >> 16)), hA[3], c3);
                c0 = __hfma2(fp8x2_to_h2((unsigned short)wA.z),         hA[4], c0);
                c1 = __hfma2(fp8x2_to_h2((unsigned short)(wA.z >> 16)), hA[5], c1);
                c2 = __hfma2(fp8x2_to_h2((unsigned short)wA.w),         hA[6], c2);
                c3 = __hfma2(fp8x2_to_h2((unsigned short)(wA.w >> 16)), hA[7], c3);
                float2 f0 = __half22float2(c0), f1 = __half22float2(c1);
                float2 f2 = __half22float2(c2), f3 = __half22float2(c3);
                a0 += (f0.x + f0.y) + (f1.x + f1.y) + (f2.x + f2.y) + (f3.x + f3.y);
                c0 = c1 = c2 = c3 = __float2half2_rn(0.f);
                c0 = __hfma2(fp8x2_to_h2((unsigned short)wB.x),         hB[0], c0);
                c1 = __hfma2(fp8x2_to_h2((unsigned short)(wB.x >> 16)), hB[1], c1);
                c2 = __hfma2(fp8x2_to_h2((unsigned short)wB.y),         hB[2], c2);
                c3 = __hfma2(fp8x2_to_h2((unsigned short)(wB.y >> 16)), hB[3], c3);
                c0 = __hfma2(fp8x2_to_h2((unsigned short)wB.z),         hB[4], c0);
                c1 = __hfma2(fp8x2_to_h2((unsigned short)(wB.z >> 16)), hB[5], c1);
                c2 = __hfma2(fp8x2_to_h2((unsigned short)wB.w),         hB[6], c2);
                c3 = __hfma2(fp8x2_to_h2((unsigned short)(wB.w >> 16)), hB[7], c3);
                f0 = __half22float2(c0); f1 = __half22float2(c1);
                f2 = __half22float2(c2); f3 = __half22float2(c3);
                a1 += (f0.x + f0.y) + (f1.x + f1.y) + (f2.x + f2.y) + (f3.x + f3.y);
            }
            float a = a0 + a1;
            #pragma unroll
            for (int off = 16; off; off >>= 1)
                a += __shfl_down_sync(0xFFFFFFFFu, a, off);

            if (lane == 0) {
                float hn = sqrtf(g_hnorm2[step]);
                float mid = a * 0.015625f + b_out[row];
                float E = 1.05f * g_drow[row] * hn +
                          0.005f * sqrtf(__uint_as_float(g_wmax2)) * hn;
                g_approx[row] = mid + E;
                keyU = pack_key(mid + E, row);
                keyL = pack_key(mid - E, row);
            }
        }
        if (lane == 0) { skeyU[wid] = keyU; skeyL[wid] = keyL; }
        __syncthreads();
        if (threadIdx.x == 0) {
            unsigned long long bU = 0ULL, bL = 0ULL;
            #pragma unroll
            for (int i = 0; i < ROWS_PER_BLK; i++) {
                if (skeyU[i] > bU) bU = skeyU[i];
                if (skeyL[i] > bL) bL = skeyL[i];
            }
            g_blockbest[blockIdx.x] = bU;
            if (bL) atomicMax(&g_amax2[step], bL);
        }
    } else {
        // -------- W_hh @ h role (fp32) --------
        const float4* __restrict__ hg = (const float4*)g_h[(step + 1) & 1];
        float4* s4 = (float4*)sbuf;
        s4[threadIdx.x] = hg[threadIdx.x];
        s4[threadIdx.x + 256] = hg[threadIdx.x + 256];
        __syncthreads();

        const int row = (int)(blockIdx.x - NBLK1) * ROWS_PER_BLK + wid;
        const float4* __restrict__ w2 = (const float4*)(W_hh + (size_t)row * HID);
        unsigned long long accA = 0ULL, accB = 0ULL, accC = 0ULL, accD = 0ULL;
        #pragma unroll
        for (int k = 0; k < HID / 256; k++) {
            f4u wa, wb, va, vb;
            wa.f = __ldcs(&w2[lane + 64 * k]);
            wb.f = __ldcs(&w2[lane + 32 + 64 * k]);
            va.f = s4[lane + 64 * k];
            vb.f = s4[lane + 32 + 64 * k];
            ffma2(accA, wa.u[0], va.u[0]);
            ffma2(accB, wa.u[1], va.u[1]);
            ffma2(accC, wb.u[0], vb.u[0]);
            ffma2(accD, wb.u[1], vb.u[1]);
        }
        float a = (f32x2_sum(accA) + f32x2_sum(accB)) + (f32x2_sum(accC) + f32x2_sum(accD));
        #pragma unroll
        for (int off = 16; off; off >>= 1)
            a += __shfl_down_sync(0xFFFFFFFFu, a, off);
        if (lane == 0) g_hh[row] = a;
    }
}

// ---------------------------------------------------------------------------
// Argmax fixup: thresh = max lower bound; any row with upper >= thresh is a
// candidate (provably includes the true argmax); exact fp32 recompute.
// ---------------------------------------------------------------------------
__global__ void __launch_bounds__(512) argmax_fixup(
    const float* __restrict__ W_out, const float* __restrict__ b_out, int step)
{
    __shared__ int s_ncand;
    __shared__ int s_cand[MAXCAND];
    __shared__ unsigned long long s_ckey[MAXCAND];

    const int tid = threadIdx.x;
    if (tid == 0) s_ncand = 0;
    __syncthreads();

    const float thresh = unpack_val(g_amax2[step]);

    for (int b = tid; b < NBLK1; b += 512) {
        unsigned long long k = __ldcg(&g_blockbest[b]);
        if (k != 0ULL && unpack_val(k) >= thresh) {
            const int r0 = b * ROWS_PER_BLK;
            const int r1 = (r0 + ROWS_PER_BLK < VOCAB) ? r0 + ROWS_PER_BLK : VOCAB;
            for (int r = r0; r < r1; r++) {
                if (__ldcg(&g_approx[r]) >= thresh) {
                    int p = atomicAdd(&s_ncand, 1);
                    if (p < MAXCAND) s_cand[p] = r;
                }
            }
        }
    }
    __syncthreads();

    int nc = s_ncand; if (nc > MAXCAND) nc = MAXCAND;
    const int wid = tid >> 5, lane = tid & 31;
    const float4* __restrict__ hp32 = (const float4*)g_h[(step + 1) & 1];

    for (int ci = wid; ci < nc; ci += 16) {
        const int r = s_cand[ci];
        const float4* __restrict__ wp = (const float4*)(W_out + (size_t)r * HID);
        float a = 0.f;
        #pragma unroll
        for (int k = 0; k < HID / 128; k++) {
            float4 w = wp[lane + 32 * k];
            float4 v = hp32[lane + 32 * k];
            a += w.x * v.x + w.y * v.y + w.z * v.z + w.w * v.w;
        }
        #pragma unroll
        for (int off = 16; off; off >>= 1)
            a += __shfl_down_sync(0xFFFFFFFFu, a, off);
        if (lane == 0) s_ckey[ci] = pack_key(a + b_out[r], r);
    }
    __syncthreads();

    if (tid == 0) {
        unsigned long long b = 0ULL;
        for (int i = 0; i < nc; i++) if (s_ckey[i] > b) b = s_ckey[i];
        g_amax[step] = b;
    }
}

// ---------------------------------------------------------------------------
// Final batched logits: out[T,VOCAB] = H @ W_out^T + b_out via wmma.
// Block = 64 t-rows x 32 vocab cols; 8 warps, 1 accum tile each.
// ---------------------------------------------------------------------------
__global__ void __launch_bounds__(256) final_logits(
    const float* __restrict__ b_out, float* __restrict__ out)
{
    __shared__ __align__(16) __half sA[64][272];     // 34KB: H chunk 64x256
    __shared__ float sC[8][16][20];                  // 10.2KB
    const int tb = blockIdx.y * 64;
    const int nb = blockIdx.x * 32;
    const int wid = threadIdx.x >> 5, lane = threadIdx.x & 31;
    const int tt = (wid & 3) * 16, nn = (wid >> 2) * 16;

    wmma::fragment<wmma::accumulator, 16, 16, 16, float> acc;
    wmma::fill_fragment(acc, 0.f);

    for (int k0 = 0; k0 < HID; k0 += 256) {
        __syncthreads();
        for (int i = threadIdx.x; i < 2048; i += 256) {     // 2048 int4
            int r = i >> 5, c = i & 31;
            *(int4*)&sA[r][c * 8] =
                *(const int4*)(g_H + (size_t)(tb + r) * HID + k0 + c * 8);
        }
        __syncthreads();
        #pragma unroll
        for (int kk = 0; kk < 256; kk += 16) {
            wmma::fragment<wmma::matrix_a, 16, 16, 16, __half, wmma::row_major> fa;
            wmma::fragment<wmma::matrix_b, 16, 16, 16, __half, wmma::col_major> fb;
            wmma::load_matrix_sync(fa, &sA[tt][kk], 272);
            wmma::load_matrix_sync(fb, g_Wout_h + (size_t)(nb + nn) * HID + k0 + kk, HID);
            wmma::mma_sync(acc, fa, fb, acc);
        }
    }
    wmma::store_matrix_sync(&sC[wid][0][0], acc, 20, wmma::mem_row_major);
    __syncwarp();
    for (int i = lane; i < 256; i += 32) {
        int r = i >> 4, c = i & 15;
        int n = nb + nn + c;
        if (n < VOCAB)
            out[(size_t)(tb + tt + r) * VOCAB + n] = sC[wid][r][c] + b_out[n];
    }
}

// ---------------------------------------------------------------------------
extern "C" void kernel_launch(void* const* d_in, const int* in_sizes, int n_in,
                              void* d_out, int out_size) {
    const float* emb   = (const float*)d_in[0];
    const float* W_ih  = (const float*)d_in[1];
    const float* W_hh  = (const float*)d_in[2];
    const float* b_ih  = (const float*)d_in[3];
    const float* b_hh  = (const float*)d_in[4];
    const float* W_out = (const float*)d_in[5];
    const float* b_out = (const float*)d_in[6];
    float* out = (float*)d_out;

    init_kernel<<<32, 256>>>();
    convert_wout<<<2048, 256>>>(W_out);

    for (int t = 0; t < T; t++) {
        step_rest_kernel<<<HID / 2, 256>>>(emb, W_ih, b_ih, b_hh, t);
        fused_kernel<<<NBLK1 + NHHB, 256>>>(W_hh, b_out, t);
        argmax_fixup<<<1, 512>>>(W_out, b_out, t);
    }
    final_logits<<<dim3(NVB, 4), 256>>>(b_out, out);
}

// round 15
// speedup vs baseline: 1.6713x; 1.6713x over previous
#include <cuda_runtime.h>
#include <cuda_fp16.h>
#include <math.h>

#define EMB   1024
#define HID   2048
#define VOCAB 50257
#define T     256
#define ROWS_PER_BLK 8
#define NBLK1 ((VOCAB + ROWS_PER_BLK - 1) / ROWS_PER_BLK)   // 6283 logits blocks
#define NHHB  (4 * HID / ROWS_PER_BLK)                       // 1024 hh blocks
#define MAXCAND 256

// Persistent device state (allocation-free scratch).
__device__ float g_h[2][HID];
__device__ __half g_h_half[HID];
__device__ float g_c[HID];
__device__ float g_hh[4 * HID];                   // W_hh @ h for next step
__device__ unsigned long long g_amax[T];          // EXACT packed argmax per step
__device__ unsigned long long g_amax2[T];         // approx global max key per step
__device__ unsigned long long g_blockbest[NBLK1]; // per-block approx max keys
__device__ float g_hnorm2[T];                     // ||h||^2 per step
__device__ unsigned g_wmax2;                      // max row-norm^2 of W_out (ordered uint)
__device__ __half g_Wout_h[(size_t)VOCAB * HID];  // fp16 W_out (~206MB)

__device__ __forceinline__ unsigned long long pack_key(float v, int row) {
    unsigned ub = __float_as_uint(v);
    ub = (ub & 0x80000000u) ? ~ub : (ub | 0x80000000u);
    return ((unsigned long long)ub << 32) |
           (unsigned long long)(0xFFFFFFFFu - (unsigned)row);
}
__device__ __forceinline__ float unpack_val(unsigned long long key) {
    unsigned t = (unsigned)(key >> 32);
    unsigned orig = (t & 0x80000000u) ? (t ^ 0x80000000u) : ~t;
    return __uint_as_float(orig);
}
__device__ __forceinline__ void ffma2(unsigned long long& acc,
                                      unsigned long long a, unsigned long long b) {
    asm("fma.rn.f32x2 %0, %1, %2, %3;" : "=l"(acc) : "l"(a), "l"(b), "l"(acc));
}
__device__ __forceinline__ float f32x2_sum(unsigned long long v) {
    float2 f = *reinterpret_cast<float2*>(&v);
    return f.x + f.y;
}
union f4u { float4 f; unsigned long long u[2]; };

// ---------------------------------------------------------------------------
// Convert W_out to fp16 AND compute max row-norm^2 (block-per-row).
// ---------------------------------------------------------------------------
__global__ void __launch_bounds__(256) convert_wout(const float* __restrict__ W) {
    __shared__ float swsum[8];
    float maxn = 0.0f;

    for (int r = blockIdx.x; r < VOCAB; r += gridDim.x) {
        const float4* __restrict__ src = (const float4*)(W + (size_t)r * HID);
        __half2* __restrict__ dst = (__half2*)(g_Wout_h + (size_t)r * HID);
        float ss = 0.0f;
        #pragma unroll
        for (int i = threadIdx.x; i < HID / 4; i += 256) {
            float4 v = src[i];
            dst[2 * i]     = __floats2half2_rn(v.x, v.y);
            dst[2 * i + 1] = __floats2half2_rn(v.z, v.w);
            ss += v.x * v.x + v.y * v.y + v.z * v.z + v.w * v.w;
        }
        #pragma unroll
        for (int off = 16; off; off >>= 1)
            ss += __shfl_down_sync(0xFFFFFFFFu, ss, off);
        if ((threadIdx.x & 31) == 0) swsum[threadIdx.x >> 5] = ss;
        __syncthreads();
        if (threadIdx.x == 0) {
            float tot = 0.0f;
            #pragma unroll
            for (int i = 0; i < 8; i++) tot += swsum[i];
            if (tot > maxn) maxn = tot;
        }
        __syncthreads();
    }
    if (threadIdx.x == 0)
        atomicMax(&g_wmax2, __float_as_uint(maxn));
}

__global__ void init_kernel() {
    int i = blockIdx.x * blockDim.x + threadIdx.x;   // grid covers 8192
    if (i < HID) {
        g_h[0][i] = 0.0f;
        g_h[1][i] = 0.0f;
        g_h_half[i] = __float2half(0.0f);
        g_c[i]    = 0.0f;
    }
    if (i < 4 * HID) g_hh[i] = 0.0f;
    if (i < T) { g_amax[i] = 0ULL; g_amax2[i] = 0ULL; g_hnorm2[i] = 0.0f; }
    if (i == 0) g_wmax2 = 0u;
}

// ---------------------------------------------------------------------------
// step_rest: gates = W_ih @ x + g_hh + biases -> LSTM cell -> h(t).
// 2048 blocks x 128 threads (1 hidden index, 4 gate-warps) = ONE dense wave.
// ---------------------------------------------------------------------------
__global__ void __launch_bounds__(128, 16) step_rest_kernel(
    const float* __restrict__ emb,
    const float* __restrict__ W_ih,
    const float* __restrict__ b_ih,
    const float* __restrict__ b_hh,
    int step)
{
    __shared__ float sx[EMB];
    __shared__ float sg[4];

    int tok = 0;
    if (step > 0)
        tok = (int)(0xFFFFFFFFu - (unsigned)(g_amax[step - 1] & 0xFFFFFFFFull));

    float* __restrict__ hnext = g_h[(step + 1) & 1];
    const float* __restrict__ xrow = emb + (size_t)tok * EMB;
    for (int i = threadIdx.x; i < EMB; i += 128) sx[i] = xrow[i];
    __syncthreads();

    const int gate = threadIdx.x >> 5;               // 0..3
    const int lane = threadIdx.x & 31;
    const int j    = blockIdx.x;                     // 0..2047
    const int row  = gate * HID + j;

    unsigned long long accA = 0ULL, accB = 0ULL, accC = 0ULL, accD = 0ULL;
    const float4* __restrict__ w1  = (const float4*)(W_ih + (size_t)row * EMB);
    const float4* __restrict__ s4x = (const float4*)sx;
    #pragma unroll
    for (int k = 0; k < EMB / 256; k++) {            // 4 dual-iters
        f4u wa, wb, va, vb;
        wa.f = __ldcs(&w1[lane + 64 * k]);
        wb.f = __ldcs(&w1[lane + 32 + 64 * k]);
        va.f = s4x[lane + 64 * k];
        vb.f = s4x[lane + 32 + 64 * k];
        ffma2(accA, wa.u[0], va.u[0]);
        ffma2(accB, wa.u[1], va.u[1]);
        ffma2(accC, wb.u[0], vb.u[0]);
        ffma2(accD, wb.u[1], vb.u[1]);
    }
    float a = (f32x2_sum(accA) + f32x2_sum(accB)) +
              (f32x2_sum(accC) + f32x2_sum(accD));
    #pragma unroll
    for (int off = 16; off; off >>= 1)
        a += __shfl_down_sync(0xFFFFFFFFu, a, off);

    if (lane == 0) sg[gate] = a + g_hh[row];
    __syncthreads();

    if (threadIdx.x == 0) {
        const int jj = j;
        float ipre = sg[0] + b_ih[jj]           + b_hh[jj];
        float fpre = sg[1] + b_ih[HID + jj]     + b_hh[HID + jj];
        float gpre = sg[2] + b_ih[2 * HID + jj] + b_hh[2 * HID + jj];
        float opre = sg[3] + b_ih[3 * HID + jj] + b_hh[3 * HID + jj];

        float ig = 1.0f / (1.0f + expf(-ipre));
        float fg = 1.0f / (1.0f + expf(-fpre));
        float gg = tanhf(gpre);
        float og = 1.0f / (1.0f + expf(-opre));

        float c = fg * g_c[jj] + ig * gg;
        float h = og * tanhf(c);
        g_c[jj]      = c;
        hnext[jj]    = h;
        g_h_half[jj] = __float2half(h);
        atomicAdd(&g_hnorm2[step], h * h);
    }
}

// ---------------------------------------------------------------------------
// Fused kernel (LPT order): blocks [0, NHHB) do the LONGER fp32 W_hh @ h rows
// first; blocks [NHHB, NHHB+NBLK1) do fp16 logits. launch_bounds(256,8) keeps
// regs <= 32 for full occupancy on the 270MB/step stream.
// ---------------------------------------------------------------------------
__global__ void __launch_bounds__(256, 8) fused_kernel(
    const float* __restrict__ W_hh,
    const float* __restrict__ b_out,
    float* __restrict__ out,
    int step)
{
    __shared__ float sbuf[HID];                      // 8KB
    __shared__ unsigned long long skey[ROWS_PER_BLK];

    const int wid  = threadIdx.x >> 5;
    const int lane = threadIdx.x & 31;

    if (blockIdx.x < NHHB) {
        // ---------------- W_hh @ h role (fp32, scheduled first) ----------------
        const float4* __restrict__ hg = (const float4*)g_h[(step + 1) & 1];
        float4* s4 = (float4*)sbuf;
        s4[threadIdx.x]       = hg[threadIdx.x];
        s4[threadIdx.x + 256] = hg[threadIdx.x + 256];
        __syncthreads();

        const int row = (int)blockIdx.x * ROWS_PER_BLK + wid;   // 0..8191
        const float4* __restrict__ w2 = (const float4*)(W_hh + (size_t)row * HID);

        unsigned long long accA = 0ULL, accB = 0ULL, accC = 0ULL, accD = 0ULL;
        #pragma unroll
        for (int k = 0; k < HID / 256; k++) {        // 8 dual-iters
            f4u wa, wb, va, vb;
            wa.f = __ldcs(&w2[lane + 64 * k]);
            wb.f = __ldcs(&w2[lane + 32 + 64 * k]);
            va.f = s4[lane + 64 * k];
            vb.f = s4[lane + 32 + 64 * k];
            ffma2(accA, wa.u[0], va.u[0]);
            ffma2(accB, wa.u[1], va.u[1]);
            ffma2(accC, wb.u[0], vb.u[0]);
            ffma2(accD, wb.u[1], vb.u[1]);
        }
        float a = (f32x2_sum(accA) + f32x2_sum(accB)) +
                  (f32x2_sum(accC) + f32x2_sum(accD));
        #pragma unroll
        for (int off = 16; off; off >>= 1)
            a += __shfl_down_sync(0xFFFFFFFFu, a, off);
        if (lane == 0) g_hh[row] = a;
    } else {
        // ---------------- fp16 logits role ----------------
        const int lbid = (int)blockIdx.x - NHHB;     // 0..NBLK1-1
        __half* sh = (__half*)sbuf;
        ((int4*)sh)[threadIdx.x] = ((const int4*)g_h_half)[threadIdx.x];  // 4KB
        __syncthreads();

        const int row = lbid * ROWS_PER_BLK + wid;
        float* __restrict__ orow = out + (size_t)step * VOCAB;

        unsigned long long key = 0ULL;
        if (row < VOCAB) {
            const int4* __restrict__ wp  = (const int4*)(g_Wout_h + (size_t)row * HID);
            const int4* __restrict__ sh4 = (const int4*)sh;

            float a0 = 0.f, a1 = 0.f;
            #pragma unroll
            for (int k = 0; k < 4; k++) {            // 4 iters x 32B/lane
                int4 w0 = __ldcs(&wp[2 * lane + 64 * k]);
                int4 w1 = __ldcs(&wp[2 * lane + 1 + 64 * k]);
                int4 h0 = sh4[2 * lane + 64 * k];
                int4 h1 = sh4[2 * lane + 1 + 64 * k];

                __half2 acc0 = __float2half2_rn(0.f);
                __half2 acc1 = __float2half2_rn(0.f);
                #pragma unroll
                for (int jq = 0; jq < 4; jq++) {
                    acc0 = __hfma2(((const __half2*)&w0)[jq], ((const __half2*)&h0)[jq], acc0);
                    acc1 = __hfma2(((const __half2*)&w1)[jq], ((const __half2*)&h1)[jq], acc1);
                }
                float2 f0 = __half22float2(acc0);
                float2 f1 = __half22float2(acc1);
                a0 += f0.x + f0.y;
                a1 += f1.x + f1.y;
            }
            float a = a0 + a1;
            #pragma unroll
            for (int off = 16; off; off >>= 1)
                a += __shfl_down_sync(0xFFFFFFFFu, a, off);

            if (lane == 0) {
                float logit = a + b_out[row];
                orow[row] = logit;
                key = pack_key(logit, row);
            }
        }
        if (lane == 0) skey[wid] = key;
        __syncthreads();

        if (threadIdx.x == 0) {
            unsigned long long b = 0ULL;
            #pragma unroll
            for (int i = 0; i < ROWS_PER_BLK; i++) if (skey[i] > b) b = skey[i];
            g_blockbest[lbid] = b;
            if (b) atomicMax(&g_amax2[step], b);
        }
    }
}

// ---------------------------------------------------------------------------
// Argmax fixup (1 block, 512 thr). thresh = approx_max - 2E with
// E = 2^-7*||W_row||max*||h|| (2.9x margin over the proven HFMA2-chain
// bound 3*2^-10*||w||*||h||). Candidates recomputed exactly in fp32.
// ---------------------------------------------------------------------------
__global__ void __launch_bounds__(512) argmax_fixup(
    const float* __restrict__ W_out,
    const float* __restrict__ b_out,
    float* __restrict__ out,
    int step)
{
    __shared__ int s_ncand;
    __shared__ int s_cand[MAXCAND];
    __shared__ unsigned long long s_ckey[MAXCAND];

    const int tid = threadIdx.x;
    if (tid == 0) s_ncand = 0;
    __syncthreads();

    const float E = 0.0078125f *              // 2^-7
                    sqrtf(__uint_as_float(g_wmax2) * g_hnorm2[step]);
    const float thresh = unpack_val(g_amax2[step]) - 2.0f * E;

    float* __restrict__ orow = out + (size_t)step * VOCAB;

    for (int b = tid; b < NBLK1; b += 512) {
        unsigned long long k = __ldcg(&g_blockbest[b]);
        if (k != 0ULL && unpack_val(k) >= thresh) {
            const int r0 = b * ROWS_PER_BLK;
            const int r1 = (r0 + ROWS_PER_BLK < VOCAB) ? r0 + ROWS_PER_BLK : VOCAB;
            for (int r = r0; r < r1; r++) {
                float v = __ldcg(&orow[r]);
                if (v >= thresh) {
                    int p = atomicAdd(&s_ncand, 1);
                    if (p < MAXCAND) s_cand[p] = r;
                }
            }
        }
    }
    __syncthreads();

    int nc = s_ncand; if (nc > MAXCAND) nc = MAXCAND;

    const int wid  = tid >> 5;
    const int lane = tid & 31;
    const float4* __restrict__ hp32 = (const float4*)g_h[(step + 1) & 1];

    for (int ci = wid; ci < nc; ci += 16) {
        const int r = s_cand[ci];
        const float4* __restrict__ wp = (const float4*)(W_out + (size_t)r * HID);
        float a = 0.f;
        #pragma unroll
        for (int k = 0; k < HID / 128; k++) {
            float4 w = wp[lane + 32 * k];
            float4 v = hp32[lane + 32 * k];
            a += w.x * v.x + w.y * v.y + w.z * v.z + w.w * v.w;
        }
        #pragma unroll
        for (int off = 16; off; off >>= 1)
            a += __shfl_down_sync(0xFFFFFFFFu, a, off);
        if (lane == 0) {
            float logit = a + b_out[r];
            orow[r] = logit;                          // exact overwrite
            s_ckey[ci] = pack_key(logit, r);
        }
    }
    __syncthreads();

    if (tid == 0) {
        unsigned long long b = 0ULL;
        for (int i = 0; i < nc; i++) if (s_ckey[i] > b) b = s_ckey[i];
        g_amax[step] = b;
    }
}

// ---------------------------------------------------------------------------
extern "C" void kernel_launch(void* const* d_in, const int* in_sizes, int n_in,
                              void* d_out, int out_size) {
    const float* emb   = (const float*)d_in[0];
    const float* W_ih  = (const float*)d_in[1];
    const float* W_hh  = (const float*)d_in[2];
    const float* b_ih  = (const float*)d_in[3];
    const float* b_hh  = (const float*)d_in[4];
    const float* W_out = (const float*)d_in[5];
    const float* b_out = (const float*)d_in[6];
    float* out = (float*)d_out;

    init_kernel<<<32, 256>>>();
    convert_wout<<<2048, 256>>>(W_out);

    for (int t = 0; t < T; t++) {
        step_rest_kernel<<<HID, 128>>>(emb, W_ih, b_ih, b_hh, t);
        fused_kernel<<<NHHB + NBLK1, 256>>>(W_hh, b_out, out, t);
        argmax_fixup<<<1, 512>>>(W_out, b_out, out, t);
    }
}